// round 13
// baseline (speedup 1.0000x reference)
#include <cuda_runtime.h>
#include <cuda_fp16.h>
#include <cstdint>
#include <cstddef>

// CapsuleLayer fused single kernel: CTA = (r, b-half of 32).
//  Phase 1: u_hat = x @ W (fp16x3, mma.sync m16n8k16, SMEM-staged W) -> smem
//  Phase 2: dynamic routing (half-warp per (b,r), register/shfl, round-11 body)
// B=64, C=32, R=1152, IN=128, OUT=16, ITERS=3.  Grid 2304, 256 thr, 2 CTAs/SM.

#define B_      64
#define C_      32
#define R_      1152
#define IN_     128
#define OUT_    16
#define STRIDE  516                        // u_hat row stride (floats), round-7 validated
#define UH_BYTES (32 * STRIDE * 4)         // 66048
#define WBUF_OFF 66560                     // 1024-aligned
#define ROWB    80                         // W smem row: 32B hi + 32B lo + 16B pad
#define WTILE_B (IN_ * ROWB)               // 10240
#define SMEM_BYTES (WBUF_OFF + 4 * WTILE_B)   // 107520 -> 2 CTAs/SM
#define NT      256

__device__ __forceinline__ unsigned h2bits(half2 h) {
    return *reinterpret_cast<unsigned*>(&h);
}
// v = hi + lo with hi,lo fp16 (packed pairs); ~22 effective bits
__device__ __forceinline__ void split2(float vx, float vy, unsigned& h, unsigned& l) {
    half2 hh = __floats2half2_rn(vx, vy);
    float2 hf = __half22float2(hh);
    half2 ll = __floats2half2_rn(vx - hf.x, vy - hf.y);
    h = h2bits(hh);
    l = h2bits(ll);
}

__device__ __forceinline__ void mma16(float& d0, float& d1, float& d2, float& d3,
                                      unsigned a0, unsigned a1, unsigned a2, unsigned a3,
                                      unsigned b0, unsigned b1) {
    asm volatile(
        "mma.sync.aligned.m16n8k16.row.col.f32.f16.f16.f32 "
        "{%0,%1,%2,%3}, {%4,%5,%6,%7}, {%8,%9}, {%0,%1,%2,%3};"
        : "+f"(d0), "+f"(d1), "+f"(d2), "+f"(d3)
        : "r"(a0), "r"(a1), "r"(a2), "r"(a3), "r"(b0), "r"(b1));
}

__device__ __forceinline__ void ldsm4t(unsigned& r0, unsigned& r1, unsigned& r2, unsigned& r3,
                                       unsigned addr) {
    asm volatile("ldmatrix.sync.aligned.m8n8.x4.trans.shared.b16 {%0,%1,%2,%3}, [%4];"
                 : "=r"(r0), "=r"(r1), "=r"(r2), "=r"(r3) : "r"(addr));
}

extern "C" __global__ void __launch_bounds__(NT, 2)
caps_fused_kernel(const float* __restrict__ X,      // (B, IN)
                  const float* __restrict__ W,      // (C, R, IN, OUT)
                  float* __restrict__ out)          // (B, R, OUT)
{
    extern __shared__ float uh_s[];                 // u_hat[b_local 32][c*16+o], stride 516
    char* wbuf = reinterpret_cast<char*>(uh_s) + WBUF_OFF;

    const int r     = blockIdx.x >> 1;
    const int half  = blockIdx.x & 1;               // b-half: global b = half*32 + b_local
    const int tid   = threadIdx.x;
    const int warp  = tid >> 5;    // 0..7
    const int lane  = tid & 31;
    const int group = lane >> 2;   // 0..7
    const int tig   = lane & 3;    // 0..3
    const int p = warp & 3;        // n-tile of 8 b
    const int g = warp >> 2;       // 0/1: c of stage

    // ===== Phase 1: GEMM =====
    // x fragments (fp16 hi/lo), ONE n-tile: b_local = 8p + group.
    unsigned xh[16], xl[16];
    {
        const float2* xr = reinterpret_cast<const float2*>(X)
                         + (size_t)(half * 32 + 8 * p + group) * (IN_ / 2);
#pragma unroll
        for (int kc = 0; kc < 8; ++kc) {
            float2 v;
            v = __ldg(xr + 8 * kc + tig);
            split2(v.x, v.y, xh[2 * kc], xl[2 * kc]);
            v = __ldg(xr + 8 * kc + tig + 4);
            split2(v.x, v.y, xh[2 * kc + 1], xl[2 * kc + 1]);
        }
    }

    // staging: thread t -> row i = t>>1, float4 pair at o4 = (t&1)*8, +4 (per tile)
    const int st_i  = tid >> 1;            // 0..127
    const int st_h  = tid & 1;
    const int st_off = st_i * OUT_ + st_h * 8;
    const size_t cstride = (size_t)R_ * (IN_ * OUT_);
    const float* Wr = W + (size_t)r * (IN_ * OUT_);

    const int lm_i = (lane & 7) + ((lane >> 4) << 3);
    const int lm_byte = lm_i * ROWB + ((lane & 8) ? 16 : 0);
    const unsigned wbuf_s = (unsigned)__cvta_generic_to_shared(wbuf);

    // prefetch stage 0 (c = 0, 1)
    float4 vA0 = __ldg(reinterpret_cast<const float4*>(Wr + 0 * cstride + st_off));
    float4 vA1 = __ldg(reinterpret_cast<const float4*>(Wr + 0 * cstride + st_off + 4));
    float4 vB0 = __ldg(reinterpret_cast<const float4*>(Wr + 1 * cstride + st_off));
    float4 vB1 = __ldg(reinterpret_cast<const float4*>(Wr + 1 * cstride + st_off + 4));

#pragma unroll 1
    for (int s = 0; s < 16; ++s) {
        const int buf = s & 1;
        // ---- split + store the 2 staged c tiles (hi/lo packed, 80B rows) ----
        {
            const int b0 = st_i * ROWB + (st_h * 8) * 2;
            char* baseA = wbuf + (size_t)(buf * 2 + 0) * WTILE_B + b0;
            char* baseB = wbuf + (size_t)(buf * 2 + 1) * WTILE_B + b0;
            unsigned h01, l01, h23, l23;
            split2(vA0.x, vA0.y, h01, l01);
            split2(vA0.z, vA0.w, h23, l23);
            *reinterpret_cast<uint2*>(baseA)      = make_uint2(h01, h23);
            *reinterpret_cast<uint2*>(baseA + 32) = make_uint2(l01, l23);
            split2(vA1.x, vA1.y, h01, l01);
            split2(vA1.z, vA1.w, h23, l23);
            *reinterpret_cast<uint2*>(baseA + 8)      = make_uint2(h01, h23);
            *reinterpret_cast<uint2*>(baseA + 8 + 32) = make_uint2(l01, l23);
            split2(vB0.x, vB0.y, h01, l01);
            split2(vB0.z, vB0.w, h23, l23);
            *reinterpret_cast<uint2*>(baseB)      = make_uint2(h01, h23);
            *reinterpret_cast<uint2*>(baseB + 32) = make_uint2(l01, l23);
            split2(vB1.x, vB1.y, h01, l01);
            split2(vB1.z, vB1.w, h23, l23);
            *reinterpret_cast<uint2*>(baseB + 8)      = make_uint2(h01, h23);
            *reinterpret_cast<uint2*>(baseB + 8 + 32) = make_uint2(l01, l23);
        }
        // ---- prefetch stage s+1 (c = 2s+2, 2s+3) ----
        if (s < 15) {
            vA0 = __ldg(reinterpret_cast<const float4*>(Wr + (size_t)(2 * s + 2) * cstride + st_off));
            vA1 = __ldg(reinterpret_cast<const float4*>(Wr + (size_t)(2 * s + 2) * cstride + st_off + 4));
            vB0 = __ldg(reinterpret_cast<const float4*>(Wr + (size_t)(2 * s + 3) * cstride + st_off));
            vB1 = __ldg(reinterpret_cast<const float4*>(Wr + (size_t)(2 * s + 3) * cstride + st_off + 4));
        }
        __syncthreads();

        // ---- MMA on c = 2s + g; 2 chains (even/odd kc) ----
        const unsigned hbase = wbuf_s + (unsigned)(buf * 2 + g) * WTILE_B + lm_byte;

        float d0 = 0.f, d1 = 0.f, d2 = 0.f, d3 = 0.f;   // even kc
        float f0 = 0.f, f1 = 0.f, f2 = 0.f, f3 = 0.f;   // odd kc
#pragma unroll
        for (int kc = 0; kc < 8; kc += 2) {
            unsigned ah0, ah1, ah2, ah3, al0, al1, al2, al3;
            unsigned bh0, bh1, bh2, bh3, bl0, bl1, bl2, bl3;
            const unsigned ka = hbase + (unsigned)(16 * kc) * ROWB;
            ldsm4t(ah0, ah1, ah2, ah3, ka);
            ldsm4t(al0, al1, al2, al3, ka + 32);
            ldsm4t(bh0, bh1, bh2, bh3, ka + 16 * ROWB);
            ldsm4t(bl0, bl1, bl2, bl3, ka + 16 * ROWB + 32);
            const int k0 = 2 * kc, k1 = 2 * kc + 2;
            mma16(d0, d1, d2, d3, ah0, ah1, ah2, ah3, xh[k0], xh[k0 + 1]);
            mma16(f0, f1, f2, f3, bh0, bh1, bh2, bh3, xh[k1], xh[k1 + 1]);
            mma16(d0, d1, d2, d3, al0, al1, al2, al3, xh[k0], xh[k0 + 1]);
            mma16(f0, f1, f2, f3, bl0, bl1, bl2, bl3, xh[k1], xh[k1 + 1]);
            mma16(d0, d1, d2, d3, ah0, ah1, ah2, ah3, xl[k0], xl[k0 + 1]);
            mma16(f0, f1, f2, f3, bh0, bh1, bh2, bh3, xl[k1], xl[k1 + 1]);
        }
        d0 += f0; d1 += f1; d2 += f2; d3 += f3;

        // ---- store D frag -> uh_s (round-5/7 validated pattern) ----
        // d0=(o=group, b=8p+2tig), d1=(group, +1), d2=(group+8, +0), d3=(group+8, +1)
        {
            const int c  = 2 * s + g;
            const int b0 = 8 * p + 2 * tig;
            float* u0 = uh_s + (size_t)b0 * STRIDE + c * OUT_ + group;
            u0[0]          = d0;
            u0[STRIDE]     = d1;
            u0[8]          = d2;
            u0[STRIDE + 8] = d3;
        }
        __syncthreads();   // wbuf[buf] consumed before refill; also final GEMM->route barrier
    }

    // ===== Phase 2: routing, half-warp per (b_local, r), 2 passes =====
    const unsigned FULL = 0xffffffffu;
    const int l16 = lane & 15;
    const int hb  = lane & 16;
    const bool h3 = (l16 & 8) != 0;
    const bool h2 = (l16 & 4) != 0;
    const bool h1 = (l16 & 2) != 0;
    const bool h0 = (l16 & 1) != 0;

#pragma unroll 1
    for (int pass = 0; pass < 2; ++pass) {
        const int b_local = pass * 16 + warp * 2 + (lane >> 4);
        const float* row = uh_s + (size_t)b_local * STRIDE;

        // uh0: c = l16, uh1: c = l16 + 16
        float uh0[16], uh1[16];
#pragma unroll
        for (int q4 = 0; q4 < 4; ++q4) {
            float4 v = *reinterpret_cast<const float4*>(row + l16 * OUT_ + 4 * q4);
            uh0[4 * q4 + 0] = v.x; uh0[4 * q4 + 1] = v.y;
            uh0[4 * q4 + 2] = v.z; uh0[4 * q4 + 3] = v.w;
            v = *reinterpret_cast<const float4*>(row + (l16 + 16) * OUT_ + 4 * q4);
            uh1[4 * q4 + 0] = v.x; uh1[4 * q4 + 1] = v.y;
            uh1[4 * q4 + 2] = v.z; uh1[4 * q4 + 3] = v.w;
        }

        float blog0 = 0.0f, blog1 = 0.0f;

#pragma unroll 1
        for (int it = 0; it < 3; ++it) {
            float cc0, cc1;
            if (it == 0) {
                cc0 = cc1 = 1.0f / 32.0f;      // softmax of zeros: exactly uniform
            } else {
                float m = fmaxf(blog0, blog1);
#pragma unroll
                for (int sh = 8; sh > 0; sh >>= 1)
                    m = fmaxf(m, __shfl_xor_sync(FULL, m, sh));
                float e0 = __expf(blog0 - m);
                float e1 = __expf(blog1 - m);
                float Z = e0 + e1;
#pragma unroll
                for (int sh = 8; sh > 0; sh >>= 1)
                    Z += __shfl_xor_sync(FULL, Z, sh);
                cc0 = e0 / Z;
                cc1 = e1 / Z;
            }

            // s[o] via 15-shfl reduce-scatter over the 16-lane half; ends with s[l16]
            float q[16];
#pragma unroll
            for (int o = 0; o < 16; ++o)
                q[o] = fmaf(cc1, uh1[o], cc0 * uh0[o]);
#pragma unroll
            for (int i = 0; i < 8; ++i) {
                float snd = h3 ? q[i] : q[i + 8];
                float kp  = h3 ? q[i + 8] : q[i];
                q[i] = kp + __shfl_xor_sync(FULL, snd, 8);
            }
#pragma unroll
            for (int i = 0; i < 4; ++i) {
                float snd = h2 ? q[i] : q[i + 4];
                float kp  = h2 ? q[i + 4] : q[i];
                q[i] = kp + __shfl_xor_sync(FULL, snd, 4);
            }
#pragma unroll
            for (int i = 0; i < 2; ++i) {
                float snd = h1 ? q[i] : q[i + 2];
                float kp  = h1 ? q[i + 2] : q[i];
                q[i] = kp + __shfl_xor_sync(FULL, snd, 2);
            }
            float sv;
            {
                float snd = h0 ? q[0] : q[1];
                float kp  = h0 ? q[1] : q[0];
                sv = kp + __shfl_xor_sync(FULL, snd, 1);
            }

            float n2 = sv * sv;
            n2 += __shfl_xor_sync(FULL, n2, 8);
            n2 += __shfl_xor_sync(FULL, n2, 4);
            n2 += __shfl_xor_sync(FULL, n2, 2);
            n2 += __shfl_xor_sync(FULL, n2, 1);

            const float nrm = sqrtf(n2);
            const float vo  = (n2 / (1.0f + n2)) * (sv / nrm);

            if (it < 2) {
                float a0 = 0.0f, a1 = 0.0f;
#pragma unroll
                for (int o2 = 0; o2 < 16; ++o2) {
                    float vv = __shfl_sync(FULL, vo, hb | o2);
                    a0 = fmaf(uh0[o2], vv, a0);
                    a1 = fmaf(uh1[o2], vv, a1);
                }
                blog0 += a0;
                blog1 += a1;
            } else {
                const int bg = half * 32 + b_local;
                out[((size_t)bg * R_ + r) * OUT_ + l16] = vo;
            }
        }
    }
}

extern "C" void kernel_launch(void* const* d_in, const int* in_sizes, int n_in,
                              void* d_out, int out_size) {
    (void)n_in; (void)out_size;
    const float* a = (const float*)d_in[0];
    const float* b = (const float*)d_in[1];
    const float* X = a;
    const float* W = b;
    if (in_sizes[0] != B_ * IN_) { X = b; W = a; }

    cudaFuncSetAttribute(caps_fused_kernel,
                         cudaFuncAttributeMaxDynamicSharedMemorySize, SMEM_BYTES);
    caps_fused_kernel<<<2 * R_, NT, SMEM_BYTES>>>(X, W, (float*)d_out);
}

// round 14
// speedup vs baseline: 1.3692x; 1.3692x over previous
#include <cuda_runtime.h>
#include <cuda_fp16.h>
#include <cstdint>
#include <cstddef>

// CapsuleLayer, two-kernel version (round-11 base + pipeline/LDG/ILP fixes).
//  K1: u_hat = x @ W  (fp16x3, mma.sync m16n8k16, SMEM-staged W, persistent CTAs,
//      256 thr / 2 CTAs per SM, single-barrier double-buffer) -> g_uhat (b, r, c, o)
//  K2: dynamic routing, HALF-warp per (b,r), 2 pairs per half-warp (ILP2).
// B=64, C=32, R=1152, IN=128, OUT=16, ITERS=3.

#define B_      64
#define C_      32
#define R_      1152
#define IN_     128
#define OUT_    16
#define ROWB    80                         // W smem row: 32B hi + 32B lo + 16B pad
#define WTILE_B (IN_ * ROWB)               // one r tile (hi+lo): 10240 B
#define SMEM1_BYTES (2 * 2 * WTILE_B)      // 2 bufs x 2 r-tiles = 40960
#define GEMM_CTAS   288                    // persistent; 8 tasks each (288*8 = 2304)
#define NT1   256
#define BSTR  ((size_t)R_ * C_ * OUT_)     // b-stride in g_uhat = 589824

__device__ float g_uhat[(size_t)B_ * R_ * C_ * OUT_];   // 151 MB scratch

__device__ __forceinline__ unsigned h2bits(half2 h) {
    return *reinterpret_cast<unsigned*>(&h);
}
// v = hi + lo with hi,lo fp16 (packed pairs); ~22 effective bits
__device__ __forceinline__ void split2(float vx, float vy, unsigned& h, unsigned& l) {
    half2 hh = __floats2half2_rn(vx, vy);
    float2 hf = __half22float2(hh);
    half2 ll = __floats2half2_rn(vx - hf.x, vy - hf.y);
    h = h2bits(hh);
    l = h2bits(ll);
}

__device__ __forceinline__ void mma16(float& d0, float& d1, float& d2, float& d3,
                                      unsigned a0, unsigned a1, unsigned a2, unsigned a3,
                                      unsigned b0, unsigned b1) {
    asm volatile(
        "mma.sync.aligned.m16n8k16.row.col.f32.f16.f16.f32 "
        "{%0,%1,%2,%3}, {%4,%5,%6,%7}, {%8,%9}, {%0,%1,%2,%3};"
        : "+f"(d0), "+f"(d1), "+f"(d2), "+f"(d3)
        : "r"(a0), "r"(a1), "r"(a2), "r"(a3), "r"(b0), "r"(b1));
}

__device__ __forceinline__ void ldsm4t(unsigned& r0, unsigned& r1, unsigned& r2, unsigned& r3,
                                       unsigned addr) {
    asm volatile("ldmatrix.sync.aligned.m8n8.x4.trans.shared.b16 {%0,%1,%2,%3}, [%4];"
                 : "=r"(r0), "=r"(r1), "=r"(r2), "=r"(r3) : "r"(addr));
}

// ===================== Kernel 1: GEMM -> g_uhat =====================
// Task t (0..2303): c = t/72, rb = t%72 -> r block rb*16..rb*16+15.
// CTA does tasks bid*8 .. bid*8+7; 64 stages of 2 r-tiles (r = rb*16 + 2*(s&7) + g).
// Warps: p = warp&3 -> b-tile of 16 (2 mma n-tiles); g = warp>>2 (0/1) -> tile of stage.
// Single-barrier double-buffer: STS(s+1) | prefetch(s+2) | MMA(s) | sync.

extern "C" __global__ void __launch_bounds__(NT1, 2)
caps_gemm_kernel(const float* __restrict__ X,      // (B, IN)
                 const float* __restrict__ W)      // (C, R, IN, OUT)
{
    extern __shared__ char wbuf[];                  // 2 bufs x 2 tiles x WTILE_B

    const int bid   = blockIdx.x;
    const int tid   = threadIdx.x;
    const int warp  = tid >> 5;    // 0..7
    const int lane  = tid & 31;
    const int group = lane >> 2;   // 0..7
    const int tig   = lane & 3;    // 0..3
    const int p = warp & 3;
    const int g = warp >> 2;       // 0/1

    // x fragments (fp16 hi/lo), two n-tiles: b = 16p+group / 16p+8+group. Loaded ONCE.
    unsigned xh0[16], xl0[16], xh1[16], xl1[16];
    {
        const float2* xr0 = reinterpret_cast<const float2*>(X) + (size_t)(16 * p + group) * (IN_ / 2);
        const float2* xr1 = reinterpret_cast<const float2*>(X) + (size_t)(16 * p + 8 + group) * (IN_ / 2);
#pragma unroll
        for (int kc = 0; kc < 8; ++kc) {
            float2 v;
            v = __ldg(xr0 + 8 * kc + tig);
            split2(v.x, v.y, xh0[2 * kc], xl0[2 * kc]);
            v = __ldg(xr0 + 8 * kc + tig + 4);
            split2(v.x, v.y, xh0[2 * kc + 1], xl0[2 * kc + 1]);
            v = __ldg(xr1 + 8 * kc + tig);
            split2(v.x, v.y, xh1[2 * kc], xl1[2 * kc]);
            v = __ldg(xr1 + 8 * kc + tig + 4);
            split2(v.x, v.y, xh1[2 * kc + 1], xl1[2 * kc + 1]);
        }
    }

    // Dense-LDG staging: thread t loads float4 at tile-flat offset 4t (rows 0-63)
    // and 4t+1024 (rows 64-127): each warp LDG = 512B contiguous (4 wavefronts).
    const int i_a  = tid >> 2;             // 0..63
    const int o4   = (tid & 3) << 2;       // 0,4,8,12
    const int ld_a = i_a * OUT_ + o4;      // == 4*tid
    const int ld_b = ld_a + 1024;          // row 64 + i_a
    const int bo_a = i_a * ROWB + o4 * 2;  // STS byte offset (hi at +0, lo at +32)
    const int bo_b = (64 + i_a) * ROWB + o4 * 2;

    const int lm_i = (lane & 7) + ((lane >> 4) << 3);
    const int lm_byte = lm_i * ROWB + ((lane & 8) ? 16 : 0);
    const unsigned wbuf_s = (unsigned)__cvta_generic_to_shared(wbuf);

    // stage -> W base of its 2 r tiles
    auto stage_base = [&](int s) -> const float* {
        int task = bid * 8 + (s >> 3);
        int c  = task / 72;
        int rb = task - c * 72;
        return W + ((size_t)c * R_ + rb * 16 + (s & 7) * 2) * (IN_ * OUT_);
    };

    // STS both tiles of one stage into buf
    auto stage_sts = [&](int buf, float4 vA0, float4 vA1, float4 vB0, float4 vB1) {
        char* baseA = wbuf + (size_t)(buf * 2 + 0) * WTILE_B;
        char* baseB = wbuf + (size_t)(buf * 2 + 1) * WTILE_B;
        unsigned h01, l01, h23, l23;
        split2(vA0.x, vA0.y, h01, l01);
        split2(vA0.z, vA0.w, h23, l23);
        *reinterpret_cast<uint2*>(baseA + bo_a)      = make_uint2(h01, h23);
        *reinterpret_cast<uint2*>(baseA + bo_a + 32) = make_uint2(l01, l23);
        split2(vA1.x, vA1.y, h01, l01);
        split2(vA1.z, vA1.w, h23, l23);
        *reinterpret_cast<uint2*>(baseA + bo_b)      = make_uint2(h01, h23);
        *reinterpret_cast<uint2*>(baseA + bo_b + 32) = make_uint2(l01, l23);
        split2(vB0.x, vB0.y, h01, l01);
        split2(vB0.z, vB0.w, h23, l23);
        *reinterpret_cast<uint2*>(baseB + bo_a)      = make_uint2(h01, h23);
        *reinterpret_cast<uint2*>(baseB + bo_a + 32) = make_uint2(l01, l23);
        split2(vB1.x, vB1.y, h01, l01);
        split2(vB1.z, vB1.w, h23, l23);
        *reinterpret_cast<uint2*>(baseB + bo_b)      = make_uint2(h01, h23);
        *reinterpret_cast<uint2*>(baseB + bo_b + 32) = make_uint2(l01, l23);
    };

    float4 vA0, vA1, vB0, vB1;
    // LDG stage 0, STS into buf 0; LDG stage 1
    {
        const float* Ws = stage_base(0);
        vA0 = __ldg(reinterpret_cast<const float4*>(Ws + ld_a));
        vA1 = __ldg(reinterpret_cast<const float4*>(Ws + ld_b));
        vB0 = __ldg(reinterpret_cast<const float4*>(Ws + 2048 + ld_a));
        vB1 = __ldg(reinterpret_cast<const float4*>(Ws + 2048 + ld_b));
        stage_sts(0, vA0, vA1, vB0, vB1);
        const float* Wn = stage_base(1);
        vA0 = __ldg(reinterpret_cast<const float4*>(Wn + ld_a));
        vA1 = __ldg(reinterpret_cast<const float4*>(Wn + ld_b));
        vB0 = __ldg(reinterpret_cast<const float4*>(Wn + 2048 + ld_a));
        vB1 = __ldg(reinterpret_cast<const float4*>(Wn + 2048 + ld_b));
    }
    __syncthreads();

#pragma unroll 1
    for (int s = 0; s < 64; ++s) {
        // ---- STS stage s+1 into buf[(s+1)&1] (safe: MMA(s-1) on that buf synced) ----
        if (s < 63)
            stage_sts((s + 1) & 1, vA0, vA1, vB0, vB1);
        // ---- prefetch stage s+2 ----
        if (s < 62) {
            const float* Wn = stage_base(s + 2);
            vA0 = __ldg(reinterpret_cast<const float4*>(Wn + ld_a));
            vA1 = __ldg(reinterpret_cast<const float4*>(Wn + ld_b));
            vB0 = __ldg(reinterpret_cast<const float4*>(Wn + 2048 + ld_a));
            vB1 = __ldg(reinterpret_cast<const float4*>(Wn + 2048 + ld_b));
        }

        // ---- MMA on tile g of stage s from buf[s&1]; 4 chains ----
        const unsigned hbase = wbuf_s + (unsigned)((s & 1) * 2 + g) * WTILE_B + lm_byte;

        float d0 = 0.f, d1 = 0.f, d2 = 0.f, d3 = 0.f;   // ntile0, even kc
        float e0 = 0.f, e1 = 0.f, e2 = 0.f, e3 = 0.f;   // ntile1, even kc
        float f0 = 0.f, f1 = 0.f, f2 = 0.f, f3 = 0.f;   // ntile0, odd kc
        float h0 = 0.f, h1 = 0.f, h2 = 0.f, h3 = 0.f;   // ntile1, odd kc
#pragma unroll
        for (int kc = 0; kc < 8; kc += 2) {
            unsigned ah0, ah1, ah2, ah3, al0, al1, al2, al3;
            unsigned bh0, bh1, bh2, bh3, bl0, bl1, bl2, bl3;
            const unsigned ka = hbase + (unsigned)(16 * kc) * ROWB;
            ldsm4t(ah0, ah1, ah2, ah3, ka);
            ldsm4t(al0, al1, al2, al3, ka + 32);
            ldsm4t(bh0, bh1, bh2, bh3, ka + 16 * ROWB);
            ldsm4t(bl0, bl1, bl2, bl3, ka + 16 * ROWB + 32);
            const int k0 = 2 * kc, k1 = 2 * kc + 2;
            mma16(d0, d1, d2, d3, ah0, ah1, ah2, ah3, xh0[k0], xh0[k0 + 1]);
            mma16(e0, e1, e2, e3, ah0, ah1, ah2, ah3, xh1[k0], xh1[k0 + 1]);
            mma16(f0, f1, f2, f3, bh0, bh1, bh2, bh3, xh0[k1], xh0[k1 + 1]);
            mma16(h0, h1, h2, h3, bh0, bh1, bh2, bh3, xh1[k1], xh1[k1 + 1]);
            mma16(d0, d1, d2, d3, al0, al1, al2, al3, xh0[k0], xh0[k0 + 1]);
            mma16(e0, e1, e2, e3, al0, al1, al2, al3, xh1[k0], xh1[k0 + 1]);
            mma16(f0, f1, f2, f3, bl0, bl1, bl2, bl3, xh0[k1], xh0[k1 + 1]);
            mma16(h0, h1, h2, h3, bl0, bl1, bl2, bl3, xh1[k1], xh1[k1 + 1]);
            mma16(d0, d1, d2, d3, ah0, ah1, ah2, ah3, xl0[k0], xl0[k0 + 1]);
            mma16(e0, e1, e2, e3, ah0, ah1, ah2, ah3, xl1[k0], xl1[k0 + 1]);
            mma16(f0, f1, f2, f3, bh0, bh1, bh2, bh3, xl0[k1], xl0[k1 + 1]);
            mma16(h0, h1, h2, h3, bh0, bh1, bh2, bh3, xl1[k1], xl1[k1 + 1]);
        }
        d0 += f0; d1 += f1; d2 += f2; d3 += f3;
        e0 += h0; e1 += h1; e2 += h2; e3 += h3;

        // ---- store D frags to g_uhat (b, r, c, o) ----
        {
            int task = bid * 8 + (s >> 3);
            int c  = task / 72;
            int rb = task - c * 72;
            int r  = rb * 16 + (s & 7) * 2 + g;
            const size_t rc = ((size_t)r * C_ + c) * OUT_;
            const int b0 = 16 * p + 2 * tig;
            float* u0 = g_uhat + (size_t)b0 * BSTR + rc + group;
            u0[0]        = d0;
            u0[BSTR]     = d1;
            u0[8]        = d2;
            u0[BSTR + 8] = d3;
            float* u1 = u0 + 8 * BSTR;
            u1[0]        = e0;
            u1[BSTR]     = e1;
            u1[8]        = e2;
            u1[BSTR + 8] = e3;
        }
        __syncthreads();   // one barrier per stage: orders MMA(s) before STS(s+2)
    }
}

// ===================== Kernel 2: dynamic routing, ILP2 =====================
// HALF-warp per (b,r); each half-warp processes TWO pairs (j=0,1) with
// interleaved instruction streams. lane = c (two c's per lane: l16, l16+16).
// Warp w handles flat pairs 4w + 2j + h (h = lane>>4).

extern "C" __global__ void __launch_bounds__(256)
caps_route_kernel(float* __restrict__ out)          // (B, R, OUT)
{
    const unsigned FULL = 0xffffffffu;
    const int lane = threadIdx.x & 31;
    const int l16  = lane & 15;
    const int hb   = lane & 16;
    const int h    = lane >> 4;
    const int w    = blockIdx.x * 8 + (threadIdx.x >> 5);   // 0..18431

    int bj[2], rj[2];
#pragma unroll
    for (int j = 0; j < 2; ++j) {
        const int pair = 4 * w + 2 * j + h;
        bj[j] = pair / R_;
        rj[j] = pair - bj[j] * R_;
    }

    // uh0[j]: u_hat[b,r, c=l16, :],  uh1[j]: c=l16+16
    float uh0[2][16], uh1[2][16];
#pragma unroll
    for (int j = 0; j < 2; ++j) {
        const float4* up = reinterpret_cast<const float4*>(
            g_uhat + ((size_t)bj[j] * R_ + rj[j]) * (C_ * OUT_) + l16 * OUT_);
#pragma unroll
        for (int q4 = 0; q4 < 4; ++q4) {
            float4 v = __ldg(up + q4);
            uh0[j][4 * q4 + 0] = v.x; uh0[j][4 * q4 + 1] = v.y;
            uh0[j][4 * q4 + 2] = v.z; uh0[j][4 * q4 + 3] = v.w;
            v = __ldg(up + 64 + q4);
            uh1[j][4 * q4 + 0] = v.x; uh1[j][4 * q4 + 1] = v.y;
            uh1[j][4 * q4 + 2] = v.z; uh1[j][4 * q4 + 3] = v.w;
        }
    }

    float blog0[2] = {0.0f, 0.0f}, blog1[2] = {0.0f, 0.0f};
    const bool h3 = (l16 & 8) != 0;
    const bool h2 = (l16 & 4) != 0;
    const bool h1 = (l16 & 2) != 0;
    const bool h0 = (l16 & 1) != 0;

#pragma unroll 1
    for (int it = 0; it < 3; ++it) {
        float cc0[2], cc1[2];
        if (it == 0) {
            cc0[0] = cc0[1] = cc1[0] = cc1[1] = 1.0f / 32.0f;
        } else {
            float m[2], Z[2], e0[2], e1[2];
#pragma unroll
            for (int j = 0; j < 2; ++j) m[j] = fmaxf(blog0[j], blog1[j]);
#pragma unroll
            for (int sh = 8; sh > 0; sh >>= 1) {
#pragma unroll
                for (int j = 0; j < 2; ++j)
                    m[j] = fmaxf(m[j], __shfl_xor_sync(FULL, m[j], sh));
            }
#pragma unroll
            for (int j = 0; j < 2; ++j) {
                e0[j] = __expf(blog0[j] - m[j]);
                e1[j] = __expf(blog1[j] - m[j]);
                Z[j] = e0[j] + e1[j];
            }
#pragma unroll
            for (int sh = 8; sh > 0; sh >>= 1) {
#pragma unroll
                for (int j = 0; j < 2; ++j)
                    Z[j] += __shfl_xor_sync(FULL, Z[j], sh);
            }
#pragma unroll
            for (int j = 0; j < 2; ++j) {
                cc0[j] = e0[j] / Z[j];
                cc1[j] = e1[j] / Z[j];
            }
        }

        // s[o] via 15-shfl reduce-scatter per j (interleaved); ends with s[l16]
        float q[2][16];
#pragma unroll
        for (int j = 0; j < 2; ++j)
#pragma unroll
            for (int o = 0; o < 16; ++o)
                q[j][o] = fmaf(cc1[j], uh1[j][o], cc0[j] * uh0[j][o]);
#pragma unroll
        for (int i = 0; i < 8; ++i)
#pragma unroll
            for (int j = 0; j < 2; ++j) {
                float snd = h3 ? q[j][i] : q[j][i + 8];
                float kp  = h3 ? q[j][i + 8] : q[j][i];
                q[j][i] = kp + __shfl_xor_sync(FULL, snd, 8);
            }
#pragma unroll
        for (int i = 0; i < 4; ++i)
#pragma unroll
            for (int j = 0; j < 2; ++j) {
                float snd = h2 ? q[j][i] : q[j][i + 4];
                float kp  = h2 ? q[j][i + 4] : q[j][i];
                q[j][i] = kp + __shfl_xor_sync(FULL, snd, 4);
            }
#pragma unroll
        for (int i = 0; i < 2; ++i)
#pragma unroll
            for (int j = 0; j < 2; ++j) {
                float snd = h1 ? q[j][i] : q[j][i + 2];
                float kp  = h1 ? q[j][i + 2] : q[j][i];
                q[j][i] = kp + __shfl_xor_sync(FULL, snd, 2);
            }
        float sv[2];
#pragma unroll
        for (int j = 0; j < 2; ++j) {
            float snd = h0 ? q[j][0] : q[j][1];
            float kp  = h0 ? q[j][1] : q[j][0];
            sv[j] = kp + __shfl_xor_sync(FULL, snd, 1);
        }

        float n2[2];
#pragma unroll
        for (int j = 0; j < 2; ++j) n2[j] = sv[j] * sv[j];
#pragma unroll
        for (int sh = 8; sh > 0; sh >>= 1) {
#pragma unroll
            for (int j = 0; j < 2; ++j)
                n2[j] += __shfl_xor_sync(FULL, n2[j], sh);
        }

        float vo[2];
#pragma unroll
        for (int j = 0; j < 2; ++j) {
            const float nrm = sqrtf(n2[j]);
            vo[j] = (n2[j] / (1.0f + n2[j])) * (sv[j] / nrm);
        }

        if (it < 2) {
            float a0[2] = {0.f, 0.f}, a1[2] = {0.f, 0.f};
#pragma unroll
            for (int o2 = 0; o2 < 16; ++o2) {
#pragma unroll
                for (int j = 0; j < 2; ++j) {
                    float vv = __shfl_sync(FULL, vo[j], hb | o2);
                    a0[j] = fmaf(uh0[j][o2], vv, a0[j]);
                    a1[j] = fmaf(uh1[j][o2], vv, a1[j]);
                }
            }
#pragma unroll
            for (int j = 0; j < 2; ++j) {
                blog0[j] += a0[j];
                blog1[j] += a1[j];
            }
        } else {
#pragma unroll
            for (int j = 0; j < 2; ++j)
                out[((size_t)bj[j] * R_ + rj[j]) * OUT_ + l16] = vo[j];
        }
    }
}

extern "C" void kernel_launch(void* const* d_in, const int* in_sizes, int n_in,
                              void* d_out, int out_size) {
    (void)n_in; (void)out_size;
    const float* a = (const float*)d_in[0];
    const float* b = (const float*)d_in[1];
    const float* X = a;
    const float* W = b;
    if (in_sizes[0] != B_ * IN_) { X = b; W = a; }

    cudaFuncSetAttribute(caps_gemm_kernel,
                         cudaFuncAttributeMaxDynamicSharedMemorySize, SMEM1_BYTES);
    caps_gemm_kernel<<<GEMM_CTAS, NT1, SMEM1_BYTES>>>(X, W);
    caps_route_kernel<<<(B_ * R_) / 32, 256>>>((float*)d_out);
}

// round 15
// speedup vs baseline: 1.4967x; 1.0931x over previous
#include <cuda_runtime.h>
#include <cuda_fp16.h>
#include <cstdint>
#include <cstddef>

// CapsuleLayer, two-kernel version: best measured halves composed.
//  K1 (round 14, 96.1us): u_hat = x @ W  (fp16x3, mma.sync m16n8k16, SMEM-staged W,
//     persistent CTAs, 2 CTAs/SM, single-barrier double-buffer, dense LDG)
//  K2 (round 11, 50.6us): routing, HALF-warp per (b,r), register/shfl.
// B=64, C=32, R=1152, IN=128, OUT=16, ITERS=3.

#define B_      64
#define C_      32
#define R_      1152
#define IN_     128
#define OUT_    16
#define ROWB    80                         // W smem row: 32B hi + 32B lo + 16B pad
#define WTILE_B (IN_ * ROWB)               // one r tile (hi+lo): 10240 B
#define SMEM1_BYTES (2 * 2 * WTILE_B)      // 2 bufs x 2 r-tiles = 40960
#define GEMM_CTAS   288                    // persistent; 8 tasks each (288*8 = 2304)
#define NT1   256
#define BSTR  ((size_t)R_ * C_ * OUT_)     // b-stride in g_uhat = 589824

__device__ float g_uhat[(size_t)B_ * R_ * C_ * OUT_];   // 151 MB scratch

__device__ __forceinline__ unsigned h2bits(half2 h) {
    return *reinterpret_cast<unsigned*>(&h);
}
// v = hi + lo with hi,lo fp16 (packed pairs); ~22 effective bits
__device__ __forceinline__ void split2(float vx, float vy, unsigned& h, unsigned& l) {
    half2 hh = __floats2half2_rn(vx, vy);
    float2 hf = __half22float2(hh);
    half2 ll = __floats2half2_rn(vx - hf.x, vy - hf.y);
    h = h2bits(hh);
    l = h2bits(ll);
}

__device__ __forceinline__ void mma16(float& d0, float& d1, float& d2, float& d3,
                                      unsigned a0, unsigned a1, unsigned a2, unsigned a3,
                                      unsigned b0, unsigned b1) {
    asm volatile(
        "mma.sync.aligned.m16n8k16.row.col.f32.f16.f16.f32 "
        "{%0,%1,%2,%3}, {%4,%5,%6,%7}, {%8,%9}, {%0,%1,%2,%3};"
        : "+f"(d0), "+f"(d1), "+f"(d2), "+f"(d3)
        : "r"(a0), "r"(a1), "r"(a2), "r"(a3), "r"(b0), "r"(b1));
}

__device__ __forceinline__ void ldsm4t(unsigned& r0, unsigned& r1, unsigned& r2, unsigned& r3,
                                       unsigned addr) {
    asm volatile("ldmatrix.sync.aligned.m8n8.x4.trans.shared.b16 {%0,%1,%2,%3}, [%4];"
                 : "=r"(r0), "=r"(r1), "=r"(r2), "=r"(r3) : "r"(addr));
}

// ===================== Kernel 1: GEMM -> g_uhat (round-14 verbatim) =====================
// Task t (0..2303): c = t/72, rb = t%72 -> r block rb*16..rb*16+15.
// CTA does tasks bid*8 .. bid*8+7; 64 stages of 2 r-tiles (r = rb*16 + 2*(s&7) + g).
// Single-barrier double-buffer: STS(s+1) | prefetch(s+2) | MMA(s) | sync.

extern "C" __global__ void __launch_bounds__(NT1, 2)
caps_gemm_kernel(const float* __restrict__ X,      // (B, IN)
                 const float* __restrict__ W)      // (C, R, IN, OUT)
{
    extern __shared__ char wbuf[];                  // 2 bufs x 2 tiles x WTILE_B

    const int bid   = blockIdx.x;
    const int tid   = threadIdx.x;
    const int warp  = tid >> 5;    // 0..7
    const int lane  = tid & 31;
    const int group = lane >> 2;   // 0..7
    const int tig   = lane & 3;    // 0..3
    const int p = warp & 3;
    const int g = warp >> 2;       // 0/1

    // x fragments (fp16 hi/lo), two n-tiles: b = 16p+group / 16p+8+group. Loaded ONCE.
    unsigned xh0[16], xl0[16], xh1[16], xl1[16];
    {
        const float2* xr0 = reinterpret_cast<const float2*>(X) + (size_t)(16 * p + group) * (IN_ / 2);
        const float2* xr1 = reinterpret_cast<const float2*>(X) + (size_t)(16 * p + 8 + group) * (IN_ / 2);
#pragma unroll
        for (int kc = 0; kc < 8; ++kc) {
            float2 v;
            v = __ldg(xr0 + 8 * kc + tig);
            split2(v.x, v.y, xh0[2 * kc], xl0[2 * kc]);
            v = __ldg(xr0 + 8 * kc + tig + 4);
            split2(v.x, v.y, xh0[2 * kc + 1], xl0[2 * kc + 1]);
            v = __ldg(xr1 + 8 * kc + tig);
            split2(v.x, v.y, xh1[2 * kc], xl1[2 * kc]);
            v = __ldg(xr1 + 8 * kc + tig + 4);
            split2(v.x, v.y, xh1[2 * kc + 1], xl1[2 * kc + 1]);
        }
    }

    // Dense-LDG staging: thread t loads float4 at tile-flat offset 4t (rows 0-63)
    // and 4t+1024 (rows 64-127): each warp LDG = 512B contiguous.
    const int i_a  = tid >> 2;             // 0..63
    const int o4   = (tid & 3) << 2;       // 0,4,8,12
    const int ld_a = i_a * OUT_ + o4;      // == 4*tid
    const int ld_b = ld_a + 1024;          // row 64 + i_a
    const int bo_a = i_a * ROWB + o4 * 2;  // STS byte offset (hi at +0, lo at +32)
    const int bo_b = (64 + i_a) * ROWB + o4 * 2;

    const int lm_i = (lane & 7) + ((lane >> 4) << 3);
    const int lm_byte = lm_i * ROWB + ((lane & 8) ? 16 : 0);
    const unsigned wbuf_s = (unsigned)__cvta_generic_to_shared(wbuf);

    auto stage_base = [&](int s) -> const float* {
        int task = bid * 8 + (s >> 3);
        int c  = task / 72;
        int rb = task - c * 72;
        return W + ((size_t)c * R_ + rb * 16 + (s & 7) * 2) * (IN_ * OUT_);
    };

    auto stage_sts = [&](int buf, float4 vA0, float4 vA1, float4 vB0, float4 vB1) {
        char* baseA = wbuf + (size_t)(buf * 2 + 0) * WTILE_B;
        char* baseB = wbuf + (size_t)(buf * 2 + 1) * WTILE_B;
        unsigned h01, l01, h23, l23;
        split2(vA0.x, vA0.y, h01, l01);
        split2(vA0.z, vA0.w, h23, l23);
        *reinterpret_cast<uint2*>(baseA + bo_a)      = make_uint2(h01, h23);
        *reinterpret_cast<uint2*>(baseA + bo_a + 32) = make_uint2(l01, l23);
        split2(vA1.x, vA1.y, h01, l01);
        split2(vA1.z, vA1.w, h23, l23);
        *reinterpret_cast<uint2*>(baseA + bo_b)      = make_uint2(h01, h23);
        *reinterpret_cast<uint2*>(baseA + bo_b + 32) = make_uint2(l01, l23);
        split2(vB0.x, vB0.y, h01, l01);
        split2(vB0.z, vB0.w, h23, l23);
        *reinterpret_cast<uint2*>(baseB + bo_a)      = make_uint2(h01, h23);
        *reinterpret_cast<uint2*>(baseB + bo_a + 32) = make_uint2(l01, l23);
        split2(vB1.x, vB1.y, h01, l01);
        split2(vB1.z, vB1.w, h23, l23);
        *reinterpret_cast<uint2*>(baseB + bo_b)      = make_uint2(h01, h23);
        *reinterpret_cast<uint2*>(baseB + bo_b + 32) = make_uint2(l01, l23);
    };

    float4 vA0, vA1, vB0, vB1;
    {
        const float* Ws = stage_base(0);
        vA0 = __ldg(reinterpret_cast<const float4*>(Ws + ld_a));
        vA1 = __ldg(reinterpret_cast<const float4*>(Ws + ld_b));
        vB0 = __ldg(reinterpret_cast<const float4*>(Ws + 2048 + ld_a));
        vB1 = __ldg(reinterpret_cast<const float4*>(Ws + 2048 + ld_b));
        stage_sts(0, vA0, vA1, vB0, vB1);
        const float* Wn = stage_base(1);
        vA0 = __ldg(reinterpret_cast<const float4*>(Wn + ld_a));
        vA1 = __ldg(reinterpret_cast<const float4*>(Wn + ld_b));
        vB0 = __ldg(reinterpret_cast<const float4*>(Wn + 2048 + ld_a));
        vB1 = __ldg(reinterpret_cast<const float4*>(Wn + 2048 + ld_b));
    }
    __syncthreads();

#pragma unroll 1
    for (int s = 0; s < 64; ++s) {
        if (s < 63)
            stage_sts((s + 1) & 1, vA0, vA1, vB0, vB1);
        if (s < 62) {
            const float* Wn = stage_base(s + 2);
            vA0 = __ldg(reinterpret_cast<const float4*>(Wn + ld_a));
            vA1 = __ldg(reinterpret_cast<const float4*>(Wn + ld_b));
            vB0 = __ldg(reinterpret_cast<const float4*>(Wn + 2048 + ld_a));
            vB1 = __ldg(reinterpret_cast<const float4*>(Wn + 2048 + ld_b));
        }

        const unsigned hbase = wbuf_s + (unsigned)((s & 1) * 2 + g) * WTILE_B + lm_byte;

        float d0 = 0.f, d1 = 0.f, d2 = 0.f, d3 = 0.f;
        float e0 = 0.f, e1 = 0.f, e2 = 0.f, e3 = 0.f;
        float f0 = 0.f, f1 = 0.f, f2 = 0.f, f3 = 0.f;
        float h0 = 0.f, h1 = 0.f, h2 = 0.f, h3 = 0.f;
#pragma unroll
        for (int kc = 0; kc < 8; kc += 2) {
            unsigned ah0, ah1, ah2, ah3, al0, al1, al2, al3;
            unsigned bh0, bh1, bh2, bh3, bl0, bl1, bl2, bl3;
            const unsigned ka = hbase + (unsigned)(16 * kc) * ROWB;
            ldsm4t(ah0, ah1, ah2, ah3, ka);
            ldsm4t(al0, al1, al2, al3, ka + 32);
            ldsm4t(bh0, bh1, bh2, bh3, ka + 16 * ROWB);
            ldsm4t(bl0, bl1, bl2, bl3, ka + 16 * ROWB + 32);
            const int k0 = 2 * kc, k1 = 2 * kc + 2;
            mma16(d0, d1, d2, d3, ah0, ah1, ah2, ah3, xh0[k0], xh0[k0 + 1]);
            mma16(e0, e1, e2, e3, ah0, ah1, ah2, ah3, xh1[k0], xh1[k0 + 1]);
            mma16(f0, f1, f2, f3, bh0, bh1, bh2, bh3, xh0[k1], xh0[k1 + 1]);
            mma16(h0, h1, h2, h3, bh0, bh1, bh2, bh3, xh1[k1], xh1[k1 + 1]);
            mma16(d0, d1, d2, d3, al0, al1, al2, al3, xh0[k0], xh0[k0 + 1]);
            mma16(e0, e1, e2, e3, al0, al1, al2, al3, xh1[k0], xh1[k0 + 1]);
            mma16(f0, f1, f2, f3, bl0, bl1, bl2, bl3, xh0[k1], xh0[k1 + 1]);
            mma16(h0, h1, h2, h3, bl0, bl1, bl2, bl3, xh1[k1], xh1[k1 + 1]);
            mma16(d0, d1, d2, d3, ah0, ah1, ah2, ah3, xl0[k0], xl0[k0 + 1]);
            mma16(e0, e1, e2, e3, ah0, ah1, ah2, ah3, xl1[k0], xl1[k0 + 1]);
            mma16(f0, f1, f2, f3, bh0, bh1, bh2, bh3, xl0[k1], xl0[k1 + 1]);
            mma16(h0, h1, h2, h3, bh0, bh1, bh2, bh3, xl1[k1], xl1[k1 + 1]);
        }
        d0 += f0; d1 += f1; d2 += f2; d3 += f3;
        e0 += h0; e1 += h1; e2 += h2; e3 += h3;

        {
            int task = bid * 8 + (s >> 3);
            int c  = task / 72;
            int rb = task - c * 72;
            int r  = rb * 16 + (s & 7) * 2 + g;
            const size_t rc = ((size_t)r * C_ + c) * OUT_;
            const int b0 = 16 * p + 2 * tig;
            float* u0 = g_uhat + (size_t)b0 * BSTR + rc + group;
            u0[0]        = d0;
            u0[BSTR]     = d1;
            u0[8]        = d2;
            u0[BSTR + 8] = d3;
            float* u1 = u0 + 8 * BSTR;
            u1[0]        = e0;
            u1[BSTR]     = e1;
            u1[8]        = e2;
            u1[BSTR + 8] = e3;
        }
        __syncthreads();
    }
}

// ===================== Kernel 2: dynamic routing (round-11 verbatim + occ hint) ====
// HALF-warp per (b,r): lanes 0-15 pair A, 16-31 pair B. lane = c (two c's per lane).

extern "C" __global__ void __launch_bounds__(256, 5)
caps_route_kernel(float* __restrict__ out)          // (B, R, OUT)
{
    const unsigned FULL = 0xffffffffu;
    const int lane = threadIdx.x & 31;
    const int l16  = lane & 15;
    const int hb   = lane & 16;
    const int pair = (blockIdx.x * 8 + (threadIdx.x >> 5)) * 2 + (lane >> 4);
    const int b = pair / R_;
    const int r = pair - b * R_;

    float uh0[16], uh1[16];
    {
        const float4* up = reinterpret_cast<const float4*>(
            g_uhat + ((size_t)b * R_ + r) * (C_ * OUT_) + l16 * OUT_);
        float4 v;
        v = __ldg(up + 0);  uh0[0] = v.x;  uh0[1] = v.y;  uh0[2] = v.z;  uh0[3] = v.w;
        v = __ldg(up + 1);  uh0[4] = v.x;  uh0[5] = v.y;  uh0[6] = v.z;  uh0[7] = v.w;
        v = __ldg(up + 2);  uh0[8] = v.x;  uh0[9] = v.y;  uh0[10] = v.z; uh0[11] = v.w;
        v = __ldg(up + 3);  uh0[12] = v.x; uh0[13] = v.y; uh0[14] = v.z; uh0[15] = v.w;
        v = __ldg(up + 64); uh1[0] = v.x;  uh1[1] = v.y;  uh1[2] = v.z;  uh1[3] = v.w;
        v = __ldg(up + 65); uh1[4] = v.x;  uh1[5] = v.y;  uh1[6] = v.z;  uh1[7] = v.w;
        v = __ldg(up + 66); uh1[8] = v.x;  uh1[9] = v.y;  uh1[10] = v.z; uh1[11] = v.w;
        v = __ldg(up + 67); uh1[12] = v.x; uh1[13] = v.y; uh1[14] = v.z; uh1[15] = v.w;
    }

    float blog0 = 0.0f, blog1 = 0.0f;
    const bool h3 = (l16 & 8) != 0;
    const bool h2 = (l16 & 4) != 0;
    const bool h1 = (l16 & 2) != 0;
    const bool h0 = (l16 & 1) != 0;

#pragma unroll 1
    for (int it = 0; it < 3; ++it) {
        float cc0, cc1;
        if (it == 0) {
            cc0 = cc1 = 1.0f / 32.0f;
        } else {
            float m = fmaxf(blog0, blog1);
#pragma unroll
            for (int s = 8; s > 0; s >>= 1)
                m = fmaxf(m, __shfl_xor_sync(FULL, m, s));
            float e0 = __expf(blog0 - m);
            float e1 = __expf(blog1 - m);
            float Z = e0 + e1;
#pragma unroll
            for (int s = 8; s > 0; s >>= 1)
                Z += __shfl_xor_sync(FULL, Z, s);
            cc0 = e0 / Z;
            cc1 = e1 / Z;
        }

        float q[16];
#pragma unroll
        for (int o = 0; o < 16; ++o)
            q[o] = fmaf(cc1, uh1[o], cc0 * uh0[o]);
#pragma unroll
        for (int i = 0; i < 8; ++i) {
            float snd = h3 ? q[i] : q[i + 8];
            float kp  = h3 ? q[i + 8] : q[i];
            q[i] = kp + __shfl_xor_sync(FULL, snd, 8);
        }
#pragma unroll
        for (int i = 0; i < 4; ++i) {
            float snd = h2 ? q[i] : q[i + 4];
            float kp  = h2 ? q[i + 4] : q[i];
            q[i] = kp + __shfl_xor_sync(FULL, snd, 4);
        }
#pragma unroll
        for (int i = 0; i < 2; ++i) {
            float snd = h1 ? q[i] : q[i + 2];
            float kp  = h1 ? q[i + 2] : q[i];
            q[i] = kp + __shfl_xor_sync(FULL, snd, 2);
        }
        float sv;
        {
            float snd = h0 ? q[0] : q[1];
            float kp  = h0 ? q[1] : q[0];
            sv = kp + __shfl_xor_sync(FULL, snd, 1);
        }

        float n2 = sv * sv;
        n2 += __shfl_xor_sync(FULL, n2, 8);
        n2 += __shfl_xor_sync(FULL, n2, 4);
        n2 += __shfl_xor_sync(FULL, n2, 2);
        n2 += __shfl_xor_sync(FULL, n2, 1);

        const float nrm = sqrtf(n2);
        const float vo  = (n2 / (1.0f + n2)) * (sv / nrm);

        if (it < 2) {
            float a0 = 0.0f, a1 = 0.0f;
#pragma unroll
            for (int o2 = 0; o2 < 16; ++o2) {
                float vv = __shfl_sync(FULL, vo, hb | o2);
                a0 = fmaf(uh0[o2], vv, a0);
                a1 = fmaf(uh1[o2], vv, a1);
            }
            blog0 += a0;
            blog1 += a1;
        } else {
            out[((size_t)b * R_ + r) * OUT_ + l16] = vo;
        }
    }
}

extern "C" void kernel_launch(void* const* d_in, const int* in_sizes, int n_in,
                              void* d_out, int out_size) {
    (void)n_in; (void)out_size;
    const float* a = (const float*)d_in[0];
    const float* b = (const float*)d_in[1];
    const float* X = a;
    const float* W = b;
    if (in_sizes[0] != B_ * IN_) { X = b; W = a; }

    cudaFuncSetAttribute(caps_gemm_kernel,
                         cudaFuncAttributeMaxDynamicSharedMemorySize, SMEM1_BYTES);
    caps_gemm_kernel<<<GEMM_CTAS, NT1, SMEM1_BYTES>>>(X, W);
    caps_route_kernel<<<(B_ * R_) / 16, 256>>>((float*)d_out);
}

// round 16
// speedup vs baseline: 1.5026x; 1.0039x over previous
#include <cuda_runtime.h>
#include <cuda_fp16.h>
#include <cstdint>
#include <cstddef>

// CapsuleLayer, two-kernel version. Round-15 base (146.8us) + g_uhat layout
// swapped to (r, b, c, o) for K1 write locality (single-page stage writes).
//  K1: u_hat = x @ W  (fp16x3, mma.sync m16n8k16, SMEM-staged W, persistent CTAs,
//      2 CTAs/SM, single-barrier double-buffer, dense LDG)
//  K2: routing, HALF-warp per (b,r), register/shfl (round-11/15 body).
// B=64, C=32, R=1152, IN=128, OUT=16, ITERS=3.

#define B_      64
#define C_      32
#define R_      1152
#define IN_     128
#define OUT_    16
#define ROWB    80                         // W smem row: 32B hi + 32B lo + 16B pad
#define WTILE_B (IN_ * ROWB)               // one r tile (hi+lo): 10240 B
#define SMEM1_BYTES (2 * 2 * WTILE_B)      // 2 bufs x 2 r-tiles = 40960
#define GEMM_CTAS   288                    // persistent; 8 tasks each (288*8 = 2304)
#define NT1   256
#define CO    (C_ * OUT_)                  // 512 floats: b-stride in (r,b,c,o) layout

__device__ float g_uhat[(size_t)R_ * B_ * C_ * OUT_];   // 151 MB scratch, (r,b,c,o)

__device__ __forceinline__ unsigned h2bits(half2 h) {
    return *reinterpret_cast<unsigned*>(&h);
}
// v = hi + lo with hi,lo fp16 (packed pairs); ~22 effective bits
__device__ __forceinline__ void split2(float vx, float vy, unsigned& h, unsigned& l) {
    half2 hh = __floats2half2_rn(vx, vy);
    float2 hf = __half22float2(hh);
    half2 ll = __floats2half2_rn(vx - hf.x, vy - hf.y);
    h = h2bits(hh);
    l = h2bits(ll);
}

__device__ __forceinline__ void mma16(float& d0, float& d1, float& d2, float& d3,
                                      unsigned a0, unsigned a1, unsigned a2, unsigned a3,
                                      unsigned b0, unsigned b1) {
    asm volatile(
        "mma.sync.aligned.m16n8k16.row.col.f32.f16.f16.f32 "
        "{%0,%1,%2,%3}, {%4,%5,%6,%7}, {%8,%9}, {%0,%1,%2,%3};"
        : "+f"(d0), "+f"(d1), "+f"(d2), "+f"(d3)
        : "r"(a0), "r"(a1), "r"(a2), "r"(a3), "r"(b0), "r"(b1));
}

__device__ __forceinline__ void ldsm4t(unsigned& r0, unsigned& r1, unsigned& r2, unsigned& r3,
                                       unsigned addr) {
    asm volatile("ldmatrix.sync.aligned.m8n8.x4.trans.shared.b16 {%0,%1,%2,%3}, [%4];"
                 : "=r"(r0), "=r"(r1), "=r"(r2), "=r"(r3) : "r"(addr));
}

// ===================== Kernel 1: GEMM -> g_uhat (r,b,c,o) =====================
// Task t (0..2303): c = t/72, rb = t%72 -> r block rb*16..rb*16+15.
// CTA does tasks bid*8 .. bid*8+7; 64 stages of 2 r-tiles (r = rb*16 + 2*(s&7) + g).
// Single-barrier double-buffer: STS(s+1) | prefetch(s+2) | MMA(s) | sync.

extern "C" __global__ void __launch_bounds__(NT1, 2)
caps_gemm_kernel(const float* __restrict__ X,      // (B, IN)
                 const float* __restrict__ W)      // (C, R, IN, OUT)
{
    extern __shared__ char wbuf[];                  // 2 bufs x 2 tiles x WTILE_B

    const int bid   = blockIdx.x;
    const int tid   = threadIdx.x;
    const int warp  = tid >> 5;    // 0..7
    const int lane  = tid & 31;
    const int group = lane >> 2;   // 0..7
    const int tig   = lane & 3;    // 0..3
    const int p = warp & 3;
    const int g = warp >> 2;       // 0/1

    // x fragments (fp16 hi/lo), two n-tiles: b = 16p+group / 16p+8+group. Loaded ONCE.
    unsigned xh0[16], xl0[16], xh1[16], xl1[16];
    {
        const float2* xr0 = reinterpret_cast<const float2*>(X) + (size_t)(16 * p + group) * (IN_ / 2);
        const float2* xr1 = reinterpret_cast<const float2*>(X) + (size_t)(16 * p + 8 + group) * (IN_ / 2);
#pragma unroll
        for (int kc = 0; kc < 8; ++kc) {
            float2 v;
            v = __ldg(xr0 + 8 * kc + tig);
            split2(v.x, v.y, xh0[2 * kc], xl0[2 * kc]);
            v = __ldg(xr0 + 8 * kc + tig + 4);
            split2(v.x, v.y, xh0[2 * kc + 1], xl0[2 * kc + 1]);
            v = __ldg(xr1 + 8 * kc + tig);
            split2(v.x, v.y, xh1[2 * kc], xl1[2 * kc]);
            v = __ldg(xr1 + 8 * kc + tig + 4);
            split2(v.x, v.y, xh1[2 * kc + 1], xl1[2 * kc + 1]);
        }
    }

    // Dense-LDG staging: thread t loads float4 at tile-flat offset 4t (rows 0-63)
    // and 4t+1024 (rows 64-127): each warp LDG = 512B contiguous.
    const int i_a  = tid >> 2;             // 0..63
    const int o4   = (tid & 3) << 2;       // 0,4,8,12
    const int ld_a = i_a * OUT_ + o4;      // == 4*tid
    const int ld_b = ld_a + 1024;          // row 64 + i_a
    const int bo_a = i_a * ROWB + o4 * 2;  // STS byte offset (hi at +0, lo at +32)
    const int bo_b = (64 + i_a) * ROWB + o4 * 2;

    const int lm_i = (lane & 7) + ((lane >> 4) << 3);
    const int lm_byte = lm_i * ROWB + ((lane & 8) ? 16 : 0);
    const unsigned wbuf_s = (unsigned)__cvta_generic_to_shared(wbuf);

    auto stage_base = [&](int s) -> const float* {
        int task = bid * 8 + (s >> 3);
        int c  = task / 72;
        int rb = task - c * 72;
        return W + ((size_t)c * R_ + rb * 16 + (s & 7) * 2) * (IN_ * OUT_);
    };

    auto stage_sts = [&](int buf, float4 vA0, float4 vA1, float4 vB0, float4 vB1) {
        char* baseA = wbuf + (size_t)(buf * 2 + 0) * WTILE_B;
        char* baseB = wbuf + (size_t)(buf * 2 + 1) * WTILE_B;
        unsigned h01, l01, h23, l23;
        split2(vA0.x, vA0.y, h01, l01);
        split2(vA0.z, vA0.w, h23, l23);
        *reinterpret_cast<uint2*>(baseA + bo_a)      = make_uint2(h01, h23);
        *reinterpret_cast<uint2*>(baseA + bo_a + 32) = make_uint2(l01, l23);
        split2(vA1.x, vA1.y, h01, l01);
        split2(vA1.z, vA1.w, h23, l23);
        *reinterpret_cast<uint2*>(baseA + bo_b)      = make_uint2(h01, h23);
        *reinterpret_cast<uint2*>(baseA + bo_b + 32) = make_uint2(l01, l23);
        split2(vB0.x, vB0.y, h01, l01);
        split2(vB0.z, vB0.w, h23, l23);
        *reinterpret_cast<uint2*>(baseB + bo_a)      = make_uint2(h01, h23);
        *reinterpret_cast<uint2*>(baseB + bo_a + 32) = make_uint2(l01, l23);
        split2(vB1.x, vB1.y, h01, l01);
        split2(vB1.z, vB1.w, h23, l23);
        *reinterpret_cast<uint2*>(baseB + bo_b)      = make_uint2(h01, h23);
        *reinterpret_cast<uint2*>(baseB + bo_b + 32) = make_uint2(l01, l23);
    };

    float4 vA0, vA1, vB0, vB1;
    {
        const float* Ws = stage_base(0);
        vA0 = __ldg(reinterpret_cast<const float4*>(Ws + ld_a));
        vA1 = __ldg(reinterpret_cast<const float4*>(Ws + ld_b));
        vB0 = __ldg(reinterpret_cast<const float4*>(Ws + 2048 + ld_a));
        vB1 = __ldg(reinterpret_cast<const float4*>(Ws + 2048 + ld_b));
        stage_sts(0, vA0, vA1, vB0, vB1);
        const float* Wn = stage_base(1);
        vA0 = __ldg(reinterpret_cast<const float4*>(Wn + ld_a));
        vA1 = __ldg(reinterpret_cast<const float4*>(Wn + ld_b));
        vB0 = __ldg(reinterpret_cast<const float4*>(Wn + 2048 + ld_a));
        vB1 = __ldg(reinterpret_cast<const float4*>(Wn + 2048 + ld_b));
    }
    __syncthreads();

#pragma unroll 1
    for (int s = 0; s < 64; ++s) {
        if (s < 63)
            stage_sts((s + 1) & 1, vA0, vA1, vB0, vB1);
        if (s < 62) {
            const float* Wn = stage_base(s + 2);
            vA0 = __ldg(reinterpret_cast<const float4*>(Wn + ld_a));
            vA1 = __ldg(reinterpret_cast<const float4*>(Wn + ld_b));
            vB0 = __ldg(reinterpret_cast<const float4*>(Wn + 2048 + ld_a));
            vB1 = __ldg(reinterpret_cast<const float4*>(Wn + 2048 + ld_b));
        }

        const unsigned hbase = wbuf_s + (unsigned)((s & 1) * 2 + g) * WTILE_B + lm_byte;

        float d0 = 0.f, d1 = 0.f, d2 = 0.f, d3 = 0.f;
        float e0 = 0.f, e1 = 0.f, e2 = 0.f, e3 = 0.f;
        float f0 = 0.f, f1 = 0.f, f2 = 0.f, f3 = 0.f;
        float h0 = 0.f, h1 = 0.f, h2 = 0.f, h3 = 0.f;
#pragma unroll
        for (int kc = 0; kc < 8; kc += 2) {
            unsigned ah0, ah1, ah2, ah3, al0, al1, al2, al3;
            unsigned bh0, bh1, bh2, bh3, bl0, bl1, bl2, bl3;
            const unsigned ka = hbase + (unsigned)(16 * kc) * ROWB;
            ldsm4t(ah0, ah1, ah2, ah3, ka);
            ldsm4t(al0, al1, al2, al3, ka + 32);
            ldsm4t(bh0, bh1, bh2, bh3, ka + 16 * ROWB);
            ldsm4t(bl0, bl1, bl2, bl3, ka + 16 * ROWB + 32);
            const int k0 = 2 * kc, k1 = 2 * kc + 2;
            mma16(d0, d1, d2, d3, ah0, ah1, ah2, ah3, xh0[k0], xh0[k0 + 1]);
            mma16(e0, e1, e2, e3, ah0, ah1, ah2, ah3, xh1[k0], xh1[k0 + 1]);
            mma16(f0, f1, f2, f3, bh0, bh1, bh2, bh3, xh0[k1], xh0[k1 + 1]);
            mma16(h0, h1, h2, h3, bh0, bh1, bh2, bh3, xh1[k1], xh1[k1 + 1]);
            mma16(d0, d1, d2, d3, al0, al1, al2, al3, xh0[k0], xh0[k0 + 1]);
            mma16(e0, e1, e2, e3, al0, al1, al2, al3, xh1[k0], xh1[k0 + 1]);
            mma16(f0, f1, f2, f3, bl0, bl1, bl2, bl3, xh0[k1], xh0[k1 + 1]);
            mma16(h0, h1, h2, h3, bl0, bl1, bl2, bl3, xh1[k1], xh1[k1 + 1]);
            mma16(d0, d1, d2, d3, ah0, ah1, ah2, ah3, xl0[k0], xl0[k0 + 1]);
            mma16(e0, e1, e2, e3, ah0, ah1, ah2, ah3, xl1[k0], xl1[k0 + 1]);
            mma16(f0, f1, f2, f3, bh0, bh1, bh2, bh3, xl0[k1], xl0[k1 + 1]);
            mma16(h0, h1, h2, h3, bh0, bh1, bh2, bh3, xl1[k1], xl1[k1 + 1]);
        }
        d0 += f0; d1 += f1; d2 += f2; d3 += f3;
        e0 += h0; e1 += h1; e2 += h2; e3 += h3;

        // ---- store D frags to g_uhat (r, b, c, o): stage spans one 128KB region ----
        {
            int task = bid * 8 + (s >> 3);
            int c  = task / 72;
            int rb = task - c * 72;
            int r  = rb * 16 + (s & 7) * 2 + g;
            const int b0 = 16 * p + 2 * tig;
            float* u0 = g_uhat + ((size_t)r * B_ + b0) * CO + c * OUT_ + group;
            u0[0]      = d0;      // (b0,   o=group)
            u0[CO]     = d1;      // (b0+1, o=group)
            u0[8]      = d2;      // (b0,   o=group+8)
            u0[CO + 8] = d3;      // (b0+1, o=group+8)
            float* u1 = u0 + 8 * CO;
            u1[0]      = e0;
            u1[CO]     = e1;
            u1[8]      = e2;
            u1[CO + 8] = e3;
        }
        __syncthreads();
    }
}

// ===================== Kernel 2: dynamic routing (round-15 body, (r,b,c,o) reads) ====
// HALF-warp per (b,r): lanes 0-15 pair A, 16-31 pair B. lane = c (two c's per lane).

extern "C" __global__ void __launch_bounds__(256, 5)
caps_route_kernel(float* __restrict__ out)          // (B, R, OUT)
{
    const unsigned FULL = 0xffffffffu;
    const int lane = threadIdx.x & 31;
    const int l16  = lane & 15;
    const int hb   = lane & 16;
    const int pair = (blockIdx.x * 8 + (threadIdx.x >> 5)) * 2 + (lane >> 4);
    const int b = pair / R_;
    const int r = pair - b * R_;

    float uh0[16], uh1[16];
    {
        const float4* up = reinterpret_cast<const float4*>(
            g_uhat + ((size_t)r * B_ + b) * CO + l16 * OUT_);
        float4 v;
        v = __ldg(up + 0);  uh0[0] = v.x;  uh0[1] = v.y;  uh0[2] = v.z;  uh0[3] = v.w;
        v = __ldg(up + 1);  uh0[4] = v.x;  uh0[5] = v.y;  uh0[6] = v.z;  uh0[7] = v.w;
        v = __ldg(up + 2);  uh0[8] = v.x;  uh0[9] = v.y;  uh0[10] = v.z; uh0[11] = v.w;
        v = __ldg(up + 3);  uh0[12] = v.x; uh0[13] = v.y; uh0[14] = v.z; uh0[15] = v.w;
        v = __ldg(up + 64); uh1[0] = v.x;  uh1[1] = v.y;  uh1[2] = v.z;  uh1[3] = v.w;
        v = __ldg(up + 65); uh1[4] = v.x;  uh1[5] = v.y;  uh1[6] = v.z;  uh1[7] = v.w;
        v = __ldg(up + 66); uh1[8] = v.x;  uh1[9] = v.y;  uh1[10] = v.z; uh1[11] = v.w;
        v = __ldg(up + 67); uh1[12] = v.x; uh1[13] = v.y; uh1[14] = v.z; uh1[15] = v.w;
    }

    float blog0 = 0.0f, blog1 = 0.0f;
    const bool h3 = (l16 & 8) != 0;
    const bool h2 = (l16 & 4) != 0;
    const bool h1 = (l16 & 2) != 0;
    const bool h0 = (l16 & 1) != 0;

#pragma unroll 1
    for (int it = 0; it < 3; ++it) {
        float cc0, cc1;
        if (it == 0) {
            cc0 = cc1 = 1.0f / 32.0f;      // softmax of zeros: exactly uniform
        } else {
            float m = fmaxf(blog0, blog1);
#pragma unroll
            for (int s = 8; s > 0; s >>= 1)
                m = fmaxf(m, __shfl_xor_sync(FULL, m, s));
            float e0 = __expf(blog0 - m);
            float e1 = __expf(blog1 - m);
            float Z = e0 + e1;
#pragma unroll
            for (int s = 8; s > 0; s >>= 1)
                Z += __shfl_xor_sync(FULL, Z, s);
            cc0 = e0 / Z;
            cc1 = e1 / Z;
        }

        float q[16];
#pragma unroll
        for (int o = 0; o < 16; ++o)
            q[o] = fmaf(cc1, uh1[o], cc0 * uh0[o]);
#pragma unroll
        for (int i = 0; i < 8; ++i) {
            float snd = h3 ? q[i] : q[i + 8];
            float kp  = h3 ? q[i + 8] : q[i];
            q[i] = kp + __shfl_xor_sync(FULL, snd, 8);
        }
#pragma unroll
        for (int i = 0; i < 4; ++i) {
            float snd = h2 ? q[i] : q[i + 4];
            float kp  = h2 ? q[i + 4] : q[i];
            q[i] = kp + __shfl_xor_sync(FULL, snd, 4);
        }
#pragma unroll
        for (int i = 0; i < 2; ++i) {
            float snd = h1 ? q[i] : q[i + 2];
            float kp  = h1 ? q[i + 2] : q[i];
            q[i] = kp + __shfl_xor_sync(FULL, snd, 2);
        }
        float sv;
        {
            float snd = h0 ? q[0] : q[1];
            float kp  = h0 ? q[1] : q[0];
            sv = kp + __shfl_xor_sync(FULL, snd, 1);
        }

        float n2 = sv * sv;
        n2 += __shfl_xor_sync(FULL, n2, 8);
        n2 += __shfl_xor_sync(FULL, n2, 4);
        n2 += __shfl_xor_sync(FULL, n2, 2);
        n2 += __shfl_xor_sync(FULL, n2, 1);

        const float nrm = sqrtf(n2);
        const float vo  = (n2 / (1.0f + n2)) * (sv / nrm);

        if (it < 2) {
            float a0 = 0.0f, a1 = 0.0f;
#pragma unroll
            for (int o2 = 0; o2 < 16; ++o2) {
                float vv = __shfl_sync(FULL, vo, hb | o2);
                a0 = fmaf(uh0[o2], vv, a0);
                a1 = fmaf(uh1[o2], vv, a1);
            }
            blog0 += a0;
            blog1 += a1;
        } else {
            out[((size_t)b * R_ + r) * OUT_ + l16] = vo;
        }
    }
}

extern "C" void kernel_launch(void* const* d_in, const int* in_sizes, int n_in,
                              void* d_out, int out_size) {
    (void)n_in; (void)out_size;
    const float* a = (const float*)d_in[0];
    const float* b = (const float*)d_in[1];
    const float* X = a;
    const float* W = b;
    if (in_sizes[0] != B_ * IN_) { X = b; W = a; }

    cudaFuncSetAttribute(caps_gemm_kernel,
                         cudaFuncAttributeMaxDynamicSharedMemorySize, SMEM1_BYTES);
    caps_gemm_kernel<<<GEMM_CTAS, NT1, SMEM1_BYTES>>>(X, W);
    caps_route_kernel<<<(B_ * R_) / 16, 256>>>((float*)d_out);
}